// round 1
// baseline (speedup 1.0000x reference)
#include <cuda_runtime.h>
#include <cuda_bf16.h>
#include <math.h>

#define NTOK 4096
#define NEXP 8
#define CDIM 768
#define HID  3072
#define TM   64
#define PADN (NTOK + NEXP * TM)      // 4608
#define NTILES (PADN / TM)           // 72

// Scratch (allocation-free rule: __device__ globals)
__device__ int   g_perm[PADN];
__device__ int   g_tile_expert[NTILES];
__device__ float g_h[(size_t)PADN * HID];   // ~57 MB

// ---------------------------------------------------------------------------
// Kernel 1: route — histogram, padded offsets, scatter token indices.
// Single block so shared-memory counters are trivially reset each launch.
// ---------------------------------------------------------------------------
__global__ void route_kernel(const int* __restrict__ mapped) {
    __shared__ int cnt[NEXP];
    __shared__ int off[NEXP];
    __shared__ int fill[NEXP];
    int tid = threadIdx.x;
    if (tid < NEXP) { cnt[tid] = 0; fill[tid] = 0; }
    __syncthreads();
    for (int i = tid; i < NTOK; i += blockDim.x)
        atomicAdd(&cnt[mapped[i]], 1);
    __syncthreads();
    if (tid == 0) {
        int o = 0;
        for (int e = 0; e < NEXP; e++) {
            off[e] = o;
            int tiles = (cnt[e] + TM - 1) / TM;
            for (int t = 0; t < tiles; t++) g_tile_expert[o / TM + t] = e;
            o += tiles * TM;
        }
        for (int t = o / TM; t < NTILES; t++) g_tile_expert[t] = -1;
    }
    __syncthreads();
    for (int i = tid; i < PADN; i += blockDim.x) g_perm[i] = -1;
    __syncthreads();
    for (int i = tid; i < NTOK; i += blockDim.x) {
        int e = mapped[i];
        int pos = off[e] + atomicAdd(&fill[e], 1);
        g_perm[pos] = i;
    }
}

// ---------------------------------------------------------------------------
// Kernel 2: up-projection. Per 64-token tile (single expert) x 64 HID cols:
//   G = x@Wg + bg ; I = x@Wi + bi ; h = silu(G) * I  -> g_h
// BM=64, BN=64, BK=16, 256 threads, 4x4 outputs/thread (x2 matrices).
// ---------------------------------------------------------------------------
__global__ __launch_bounds__(256) void up_kernel(
    const float* __restrict__ x,
    const float* __restrict__ Wg, const float* __restrict__ bg,
    const float* __restrict__ Wi, const float* __restrict__ bi)
{
    int t = blockIdx.y;
    int e = g_tile_expert[t];
    if (e < 0) return;
    int n0 = blockIdx.x * 64;

    __shared__ float xs[16][64];   // [k][m]
    __shared__ float gsm[16][64];  // [k][n]
    __shared__ float ism[16][64];  // [k][n]

    int tid = threadIdx.x;
    int tn  = (tid & 15) * 4;      // n offset (4 cols)
    int tmr = (tid >> 4) * 4;      // m offset (4 rows)

    // x loader: one float4 per thread; lr conflict-free across a warp
    int lr = tid & 63;             // token row within tile
    int lc = (tid >> 6) * 4;       // k offset within BK
    int prow = g_perm[t * TM + lr];
    const float* xrow = (prow >= 0) ? (x + (size_t)prow * CDIM) : nullptr;

    // weight loader: one float4 per thread
    int wr = tid >> 4;             // k row within BK
    int wc = (tid & 15) * 4;       // n offset
    const float* wg_e = Wg + (size_t)e * CDIM * HID;
    const float* wi_e = Wi + (size_t)e * CDIM * HID;

    float accG[4][4] = {};
    float accI[4][4] = {};

    for (int k0 = 0; k0 < CDIM; k0 += 16) {
        float4 xv = xrow ? *(const float4*)(xrow + k0 + lc)
                         : make_float4(0.f, 0.f, 0.f, 0.f);
        float4 gv = *(const float4*)(wg_e + (size_t)(k0 + wr) * HID + n0 + wc);
        float4 iv = *(const float4*)(wi_e + (size_t)(k0 + wr) * HID + n0 + wc);
        __syncthreads();
        xs[lc + 0][lr] = xv.x; xs[lc + 1][lr] = xv.y;
        xs[lc + 2][lr] = xv.z; xs[lc + 3][lr] = xv.w;
        *(float4*)&gsm[wr][wc] = gv;
        *(float4*)&ism[wr][wc] = iv;
        __syncthreads();
        #pragma unroll
        for (int k = 0; k < 16; k++) {
            float4 a  = *(const float4*)&xs[k][tmr];
            float4 bG = *(const float4*)&gsm[k][tn];
            float4 bI = *(const float4*)&ism[k][tn];
            float am[4] = {a.x, a.y, a.z, a.w};
            float gB[4] = {bG.x, bG.y, bG.z, bG.w};
            float iB[4] = {bI.x, bI.y, bI.z, bI.w};
            #pragma unroll
            for (int i = 0; i < 4; i++)
                #pragma unroll
                for (int j = 0; j < 4; j++) {
                    accG[i][j] += am[i] * gB[j];
                    accI[i][j] += am[i] * iB[j];
                }
        }
    }

    float4 bgv = *(const float4*)(bg + (size_t)e * HID + n0 + tn);
    float4 biv = *(const float4*)(bi + (size_t)e * HID + n0 + tn);
    float bGa[4] = {bgv.x, bgv.y, bgv.z, bgv.w};
    float bIa[4] = {biv.x, biv.y, biv.z, biv.w};

    #pragma unroll
    for (int i = 0; i < 4; i++) {
        size_t p = (size_t)(t * TM + tmr + i);
        float4 hv;
        float* hp = (float*)&hv;
        #pragma unroll
        for (int j = 0; j < 4; j++) {
            float g = accG[i][j] + bGa[j];
            float v = accI[i][j] + bIa[j];
            float s = g / (1.0f + expf(-g));   // silu
            hp[j] = s * v;
        }
        *(float4*)&g_h[p * HID + n0 + tn] = hv;
    }
}

// ---------------------------------------------------------------------------
// Kernel 3: down-projection + scatter: y = h @ Wo + bo -> out[perm]
// ---------------------------------------------------------------------------
__global__ __launch_bounds__(256) void down_kernel(
    const float* __restrict__ Wo, const float* __restrict__ bo,
    float* __restrict__ out)
{
    int t = blockIdx.y;
    int e = g_tile_expert[t];
    if (e < 0) return;
    int n0 = blockIdx.x * 64;

    __shared__ float hs[16][64];   // [k][m]
    __shared__ float wsm[16][64];  // [k][n]

    int tid = threadIdx.x;
    int tn  = (tid & 15) * 4;
    int tmr = (tid >> 4) * 4;

    int lr = tid & 63;
    int lc = (tid >> 6) * 4;
    const float* hrow = g_h + (size_t)(t * TM + lr) * HID;

    int wr = tid >> 4;
    int wc = (tid & 15) * 4;
    const float* wo_e = Wo + (size_t)e * HID * CDIM;

    float acc[4][4] = {};

    for (int k0 = 0; k0 < HID; k0 += 16) {
        float4 hv = *(const float4*)(hrow + k0 + lc);
        float4 wv = *(const float4*)(wo_e + (size_t)(k0 + wr) * CDIM + n0 + wc);
        __syncthreads();
        hs[lc + 0][lr] = hv.x; hs[lc + 1][lr] = hv.y;
        hs[lc + 2][lr] = hv.z; hs[lc + 3][lr] = hv.w;
        *(float4*)&wsm[wr][wc] = wv;
        __syncthreads();
        #pragma unroll
        for (int k = 0; k < 16; k++) {
            float4 a = *(const float4*)&hs[k][tmr];
            float4 b = *(const float4*)&wsm[k][tn];
            float am[4] = {a.x, a.y, a.z, a.w};
            float bn[4] = {b.x, b.y, b.z, b.w};
            #pragma unroll
            for (int i = 0; i < 4; i++)
                #pragma unroll
                for (int j = 0; j < 4; j++)
                    acc[i][j] += am[i] * bn[j];
        }
    }

    float4 bov = *(const float4*)(bo + (size_t)e * CDIM + n0 + tn);
    float boa[4] = {bov.x, bov.y, bov.z, bov.w};

    #pragma unroll
    for (int i = 0; i < 4; i++) {
        int prow = g_perm[t * TM + tmr + i];
        if (prow < 0) continue;
        float4 yv;
        float* yp = (float*)&yv;
        #pragma unroll
        for (int j = 0; j < 4; j++) yp[j] = acc[i][j] + boa[j];
        *(float4*)&out[(size_t)prow * CDIM + n0 + tn] = yv;
    }
}

// ---------------------------------------------------------------------------
extern "C" void kernel_launch(void* const* d_in, const int* in_sizes, int n_in,
                              void* d_out, int out_size)
{
    const float* x      = (const float*)d_in[0];
    const int*   mapped = (const int*)  d_in[1];
    const float* Wg     = (const float*)d_in[2];
    const float* bg     = (const float*)d_in[3];
    const float* Wi     = (const float*)d_in[4];
    const float* bi     = (const float*)d_in[5];
    const float* Wo     = (const float*)d_in[6];
    const float* bo     = (const float*)d_in[7];
    float* out = (float*)d_out;

    route_kernel<<<1, 256>>>(mapped);

    dim3 g2(HID / 64, NTILES);     // 48 x 72
    up_kernel<<<g2, 256>>>(x, Wg, bg, Wi, bi);

    dim3 g3(CDIM / 64, NTILES);    // 12 x 72
    down_kernel<<<g3, 256>>>(Wo, bo, out);
}

// round 3
// speedup vs baseline: 1.8565x; 1.8565x over previous
#include <cuda_runtime.h>
#include <cuda_bf16.h>
#include <math.h>
#include <cstdint>

#define NTOK 4096
#define NEXP 8
#define CDIM 768
#define HID  3072
#define TM   128
#define PADN (NTOK + NEXP * TM)   // 5120
#define MTILES (PADN / TM)        // 40
#define KSTEP 32
#define NS_UP (CDIM / KSTEP)      // 24
#define NS_DN (HID / KSTEP)       // 96

#define APITCH 80    // 32 bf16 data + 8 pad, bytes
#define BPITCH 272   // 128 bf16 data + 8 pad, bytes
#define SM_A_HI 0
#define SM_A_LO 10240
#define SM_B_HI 20480
#define SM_B_LO 29184
#define SMEM_LOOP 37888
#define SMEM_EPI  67584   // 128 x 132 fp32 staging (up kernel only)

// ---------------- scratch ----------------
__device__ int g_perm[PADN];
__device__ int g_tile_expert[MTILES];
__device__ __nv_bfloat16 g_h_hi[(size_t)PADN * HID];   // 31.5 MB
__device__ __nv_bfloat16 g_h_lo[(size_t)PADN * HID];   // 31.5 MB

// ---------------- helpers ----------------
static __device__ __forceinline__ uint32_t smem_u32(const void* p) {
    uint32_t a;
    asm("{ .reg .u64 t; cvta.to.shared.u64 t, %1; cvt.u32.u64 %0, t; }" : "=r"(a) : "l"(p));
    return a;
}
static __device__ __forceinline__ void ldsm4(uint32_t* r, uint32_t a) {
    asm volatile("ldmatrix.sync.aligned.m8n8.x4.shared.b16 {%0,%1,%2,%3}, [%4];"
        : "=r"(r[0]), "=r"(r[1]), "=r"(r[2]), "=r"(r[3]) : "r"(a));
}
static __device__ __forceinline__ void ldsm4t(uint32_t* r, uint32_t a) {
    asm volatile("ldmatrix.sync.aligned.m8n8.x4.trans.shared.b16 {%0,%1,%2,%3}, [%4];"
        : "=r"(r[0]), "=r"(r[1]), "=r"(r[2]), "=r"(r[3]) : "r"(a));
}
static __device__ __forceinline__ void mma_bf16(float* c, const uint32_t* a, const uint32_t* b) {
    asm volatile("mma.sync.aligned.m16n8k16.row.col.f32.bf16.bf16.f32 "
        "{%0,%1,%2,%3}, {%4,%5,%6,%7}, {%8,%9}, {%0,%1,%2,%3};"
        : "+f"(c[0]), "+f"(c[1]), "+f"(c[2]), "+f"(c[3])
        : "r"(a[0]), "r"(a[1]), "r"(a[2]), "r"(a[3]), "r"(b[0]), "r"(b[1]));
}
static __device__ __forceinline__ void split_pair(float a, float b, uint32_t& hw, uint32_t& lw) {
    __nv_bfloat162 hp = __floats2bfloat162_rn(a, b);
    float ra = a - __low2float(hp);
    float rb = b - __high2float(hp);
    __nv_bfloat162 lp = __floats2bfloat162_rn(ra, rb);
    union { __nv_bfloat162 b2; uint32_t u; } ch, cl;
    ch.b2 = hp; cl.b2 = lp;
    hw = ch.u; lw = cl.u;
}
static __device__ __forceinline__ void split8(float4 p, float4 q, uint4& hi, uint4& lo) {
    split_pair(p.x, p.y, hi.x, lo.x);
    split_pair(p.z, p.w, hi.y, lo.y);
    split_pair(q.x, q.y, hi.z, lo.z);
    split_pair(q.z, q.w, hi.w, lo.w);
}
// A smem byte offset: row-major [128][40 bf16], 32B-granule XOR swizzle by row bit 3
static __device__ __forceinline__ int aoff(int row, int kb) {
    return row * APITCH + ((((kb >> 5) ^ (row >> 3)) & 1) << 5) + (kb & 31);
}
// B smem byte offset: [32 k][136 bf16], 16B-chunk XOR swizzle by 2*(row&7)
static __device__ __forceinline__ int boff(int krow, int chunk) {
    return krow * BPITCH + ((chunk ^ ((krow & 7) << 1)) & 15) * 16;
}

// ---------------------------------------------------------------------------
// route
// ---------------------------------------------------------------------------
__global__ void route_kernel(const int* __restrict__ mapped) {
    __shared__ int cnt[NEXP];
    __shared__ int off[NEXP];
    __shared__ int fill[NEXP];
    int tid = threadIdx.x;
    if (tid < NEXP) { cnt[tid] = 0; fill[tid] = 0; }
    __syncthreads();
    for (int i = tid; i < NTOK; i += blockDim.x) atomicAdd(&cnt[mapped[i]], 1);
    __syncthreads();
    if (tid == 0) {
        int o = 0;
        for (int e = 0; e < NEXP; e++) {
            off[e] = o;
            int tiles = (cnt[e] + TM - 1) / TM;
            for (int t = 0; t < tiles; t++) g_tile_expert[o / TM + t] = e;
            o += tiles * TM;
        }
        for (int t = o / TM; t < MTILES; t++) g_tile_expert[t] = -1;
    }
    __syncthreads();
    for (int i = tid; i < PADN; i += blockDim.x) g_perm[i] = -1;
    __syncthreads();
    for (int i = tid; i < NTOK; i += blockDim.x) {
        int e = mapped[i];
        g_perm[off[e] + atomicAdd(&fill[e], 1)] = i;
    }
}

// ---------------------------------------------------------------------------
// up GEMM: [128 tok] x [Wg 64 | Wi 64 cols], K=768, 3-pass bf16 split HMMA
// ---------------------------------------------------------------------------
__global__ __launch_bounds__(256, 1)
void up_kernel(const float* __restrict__ x,
               const float* __restrict__ Wg, const float* __restrict__ bg,
               const float* __restrict__ Wi, const float* __restrict__ bi)
{
    extern __shared__ char smem[];
    int mtile = blockIdx.x;
    int e = g_tile_expert[mtile];
    if (e < 0) return;
    int n0 = blockIdx.y * 64;  // global HID col offset (both G and I)

    int tid = threadIdx.x, lane = tid & 31, wid = tid >> 5;
    int wm = wid >> 2, wn = wid & 3;
    uint32_t sb = smem_u32(smem);

    // A loader: 16 floats per thread
    int arow = tid >> 1, ag = tid & 1;
    int prow = g_perm[mtile * TM + arow];
    const float* xp = (prow >= 0) ? x + (size_t)prow * CDIM + ag * 16 : nullptr;
    int astore = arow * APITCH + (((ag ^ (arow >> 3)) & 1) << 5);

    // B loader: 16 floats per thread; warps 0-3 -> Wg, 4-7 -> Wi
    int brow = tid & 31;
    const float* wp = ((wid < 4) ? Wg : Wi) + (size_t)e * CDIM * HID
                    + (size_t)brow * HID + n0 + (wid & 3) * 16;
    int c0 = wid * 2, r7 = (brow & 7) << 1;
    int bst0 = brow * BPITCH + ((c0 ^ r7) & 15) * 16;
    int bst1 = brow * BPITCH + (((c0 + 1) ^ r7) & 15) * 16;

    float4 av[4], bv[4];
    #pragma unroll
    for (int i = 0; i < 4; i++) {
        av[i] = xp ? *(const float4*)(xp + i * 4) : make_float4(0.f, 0.f, 0.f, 0.f);
        bv[i] = *(const float4*)(wp + i * 4);
    }

    float acc[4][4][4] = {};

    for (int s = 0; s < NS_UP; s++) {
        __syncthreads();
        {
            uint4 H0, L0, H1, L1;
            split8(av[0], av[1], H0, L0); split8(av[2], av[3], H1, L1);
            *(uint4*)(smem + SM_A_HI + astore)      = H0;
            *(uint4*)(smem + SM_A_HI + astore + 16) = H1;
            *(uint4*)(smem + SM_A_LO + astore)      = L0;
            *(uint4*)(smem + SM_A_LO + astore + 16) = L1;
            split8(bv[0], bv[1], H0, L0); split8(bv[2], bv[3], H1, L1);
            *(uint4*)(smem + SM_B_HI + bst0) = H0;
            *(uint4*)(smem + SM_B_HI + bst1) = H1;
            *(uint4*)(smem + SM_B_LO + bst0) = L0;
            *(uint4*)(smem + SM_B_LO + bst1) = L1;
        }
        __syncthreads();
        if (s + 1 < NS_UP) {
            #pragma unroll
            for (int i = 0; i < 4; i++) {
                av[i] = xp ? *(const float4*)(xp + (s + 1) * KSTEP + i * 4)
                           : make_float4(0.f, 0.f, 0.f, 0.f);
                bv[i] = *(const float4*)(wp + (size_t)(s + 1) * KSTEP * HID + i * 4);
            }
        }
        #pragma unroll
        for (int k16 = 0; k16 < 2; k16++) {
            int k0 = k16 * 16;
            uint32_t ah[4][4], al[4][4], bh[4][2], bl[4][2];
            int ar = wm * 64 + (lane & 7) + ((lane >> 3) & 1) * 8;
            int kb = (k0 + ((lane >> 4) & 1) * 8) * 2;
            #pragma unroll
            for (int mi = 0; mi < 4; mi++) {
                int o = aoff(ar + mi * 16, kb);
                ldsm4(ah[mi], sb + SM_A_HI + o);
                ldsm4(al[mi], sb + SM_A_LO + o);
            }
            int rk = k0 + (lane & 7) + ((lane >> 3) & 1) * 8;
            #pragma unroll
            for (int g = 0; g < 2; g++) {
                int ch = (wn * 32 + g * 16) / 8 + ((lane >> 4) & 1);
                int o = boff(rk, ch);
                uint32_t t[4];
                ldsm4t(t, sb + SM_B_HI + o);
                bh[2*g][0] = t[0]; bh[2*g][1] = t[1];
                bh[2*g+1][0] = t[2]; bh[2*g+1][1] = t[3];
                ldsm4t(t, sb + SM_B_LO + o);
                bl[2*g][0] = t[0]; bl[2*g][1] = t[1];
                bl[2*g+1][0] = t[2]; bl[2*g+1][1] = t[3];
            }
            #pragma unroll
            for (int mi = 0; mi < 4; mi++)
                #pragma unroll
                for (int nj = 0; nj < 4; nj++) {
                    mma_bf16(acc[mi][nj], ah[mi], bh[nj]);
                    mma_bf16(acc[mi][nj], ah[mi], bl[nj]);
                    mma_bf16(acc[mi][nj], al[mi], bh[nj]);
                }
        }
    }

    // epilogue: stage fp32 [128][132], combine G/I, SiLU, split-store h
    __syncthreads();
    float* S = (float*)smem;
    #pragma unroll
    for (int mi = 0; mi < 4; mi++) {
        int r0 = wm * 64 + mi * 16 + (lane >> 2);
        #pragma unroll
        for (int nj = 0; nj < 4; nj++) {
            int col = wn * 32 + nj * 8 + (lane & 3) * 2;
            *(float2*)&S[r0 * 132 + col]       = make_float2(acc[mi][nj][0], acc[mi][nj][1]);
            *(float2*)&S[(r0 + 8) * 132 + col] = make_float2(acc[mi][nj][2], acc[mi][nj][3]);
        }
    }
    __syncthreads();
    {
        int row = tid >> 1;
        int cb = (tid & 1) * 32;
        size_t orow = (size_t)(mtile * TM + row) * HID + n0;
        const float* bgp = bg + (size_t)e * HID + n0;
        const float* bip = bi + (size_t)e * HID + n0;
        #pragma unroll
        for (int jj = 0; jj < 32; jj += 8) {
            uint4 H, L;
            uint32_t* hp = (uint32_t*)&H;
            uint32_t* lp = (uint32_t*)&L;
            #pragma unroll
            for (int q = 0; q < 4; q++) {
                int col = cb + jj + q * 2;
                float g0 = S[row * 132 + col]     + bgp[col];
                float v0 = S[row * 132 + col+64]  + bip[col];
                float g1 = S[row * 132 + col+1]   + bgp[col+1];
                float v1 = S[row * 132 + col+65]  + bip[col+1];
                float h0 = (g0 / (1.0f + __expf(-g0))) * v0;
                float h1 = (g1 / (1.0f + __expf(-g1))) * v1;
                split_pair(h0, h1, hp[q], lp[q]);
            }
            *(uint4*)(g_h_hi + orow + cb + jj) = H;
            *(uint4*)(g_h_lo + orow + cb + jj) = L;
        }
    }
}

// ---------------------------------------------------------------------------
// down GEMM: y = h @ Wo + bo, scatter via perm. A already bf16 hi/lo.
// ---------------------------------------------------------------------------
__global__ __launch_bounds__(256, 1)
void down_kernel(const float* __restrict__ Wo, const float* __restrict__ bo,
                 float* __restrict__ out)
{
    extern __shared__ char smem[];
    int mtile = blockIdx.x;
    int e = g_tile_expert[mtile];
    if (e < 0) return;
    int n0 = blockIdx.y * 128;

    int tid = threadIdx.x, lane = tid & 31, wid = tid >> 5;
    int wm = wid >> 2, wn = wid & 3;
    uint32_t sb = smem_u32(smem);

    // A loader: 16 bf16 (32B) per array per thread
    int arow = tid >> 1, ag = tid & 1;
    const __nv_bfloat16* hh = g_h_hi + (size_t)(mtile * TM + arow) * HID + ag * 16;
    const __nv_bfloat16* hl = g_h_lo + (size_t)(mtile * TM + arow) * HID + ag * 16;
    int astore = arow * APITCH + (((ag ^ (arow >> 3)) & 1) << 5);

    // B loader
    int brow = tid & 31;
    const float* wp = Wo + (size_t)e * HID * CDIM + (size_t)brow * CDIM + n0 + wid * 16;
    int c0 = wid * 2, r7 = (brow & 7) << 1;
    int bst0 = brow * BPITCH + ((c0 ^ r7) & 15) * 16;
    int bst1 = brow * BPITCH + (((c0 + 1) ^ r7) & 15) * 16;

    uint4 Ah, Al;
    float4 bv[4];
    Ah = *(const uint4*)hh;  // 16 bf16 hi
    Al = *(const uint4*)hl;
    uint4 Ah2 = *((const uint4*)hh + 1);
    uint4 Al2 = *((const uint4*)hl + 1);
    #pragma unroll
    for (int i = 0; i < 4; i++) bv[i] = *(const float4*)(wp + i * 4);

    float acc[4][4][4] = {};

    for (int s = 0; s < NS_DN; s++) {
        __syncthreads();
        {
            *(uint4*)(smem + SM_A_HI + astore)      = Ah;
            *(uint4*)(smem + SM_A_HI + astore + 16) = Ah2;
            *(uint4*)(smem + SM_A_LO + astore)      = Al;
            *(uint4*)(smem + SM_A_LO + astore + 16) = Al2;
            uint4 H0, L0, H1, L1;
            split8(bv[0], bv[1], H0, L0); split8(bv[2], bv[3], H1, L1);
            *(uint4*)(smem + SM_B_HI + bst0) = H0;
            *(uint4*)(smem + SM_B_HI + bst1) = H1;
            *(uint4*)(smem + SM_B_LO + bst0) = L0;
            *(uint4*)(smem + SM_B_LO + bst1) = L1;
        }
        __syncthreads();
        if (s + 1 < NS_DN) {
            const __nv_bfloat16* ph = hh + (s + 1) * KSTEP;
            const __nv_bfloat16* pl = hl + (s + 1) * KSTEP;
            Ah = *(const uint4*)ph; Ah2 = *((const uint4*)ph + 1);
            Al = *(const uint4*)pl; Al2 = *((const uint4*)pl + 1);
            #pragma unroll
            for (int i = 0; i < 4; i++)
                bv[i] = *(const float4*)(wp + (size_t)(s + 1) * KSTEP * CDIM + i * 4);
        }
        #pragma unroll
        for (int k16 = 0; k16 < 2; k16++) {
            int k0 = k16 * 16;
            uint32_t ah[4][4], al[4][4], bh[4][2], bl[4][2];
            int ar = wm * 64 + (lane & 7) + ((lane >> 3) & 1) * 8;
            int kb = (k0 + ((lane >> 4) & 1) * 8) * 2;
            #pragma unroll
            for (int mi = 0; mi < 4; mi++) {
                int o = aoff(ar + mi * 16, kb);
                ldsm4(ah[mi], sb + SM_A_HI + o);
                ldsm4(al[mi], sb + SM_A_LO + o);
            }
            int rk = k0 + (lane & 7) + ((lane >> 3) & 1) * 8;
            #pragma unroll
            for (int g = 0; g < 2; g++) {
                int ch = (wn * 32 + g * 16) / 8 + ((lane >> 4) & 1);
                int o = boff(rk, ch);
                uint32_t t[4];
                ldsm4t(t, sb + SM_B_HI + o);
                bh[2*g][0] = t[0]; bh[2*g][1] = t[1];
                bh[2*g+1][0] = t[2]; bh[2*g+1][1] = t[3];
                ldsm4t(t, sb + SM_B_LO + o);
                bl[2*g][0] = t[0]; bl[2*g][1] = t[1];
                bl[2*g+1][0] = t[2]; bl[2*g+1][1] = t[3];
            }
            #pragma unroll
            for (int mi = 0; mi < 4; mi++)
                #pragma unroll
                for (int nj = 0; nj < 4; nj++) {
                    mma_bf16(acc[mi][nj], ah[mi], bh[nj]);
                    mma_bf16(acc[mi][nj], ah[mi], bl[nj]);
                    mma_bf16(acc[mi][nj], al[mi], bh[nj]);
                }
        }
    }

    // epilogue: bias + scatter via perm (direct from regs)
    const float* bop = bo + (size_t)e * CDIM;
    #pragma unroll
    for (int mi = 0; mi < 4; mi++) {
        int r0 = wm * 64 + mi * 16 + (lane >> 2);
        int p0 = g_perm[mtile * TM + r0];
        int p1 = g_perm[mtile * TM + r0 + 8];
        #pragma unroll
        for (int nj = 0; nj < 4; nj++) {
            int col = n0 + wn * 32 + nj * 8 + (lane & 3) * 2;
            float2 b = *(const float2*)(bop + col);
            if (p0 >= 0)
                *(float2*)&out[(size_t)p0 * CDIM + col] =
                    make_float2(acc[mi][nj][0] + b.x, acc[mi][nj][1] + b.y);
            if (p1 >= 0)
                *(float2*)&out[(size_t)p1 * CDIM + col] =
                    make_float2(acc[mi][nj][2] + b.x, acc[mi][nj][3] + b.y);
        }
    }
}

// ---------------------------------------------------------------------------
extern "C" void kernel_launch(void* const* d_in, const int* in_sizes, int n_in,
                              void* d_out, int out_size)
{
    const float* x      = (const float*)d_in[0];
    const int*   mapped = (const int*)  d_in[1];
    const float* Wg     = (const float*)d_in[2];
    const float* bg     = (const float*)d_in[3];
    const float* Wi     = (const float*)d_in[4];
    const float* bi     = (const float*)d_in[5];
    const float* Wo     = (const float*)d_in[6];
    const float* bo     = (const float*)d_in[7];
    float* out = (float*)d_out;

    cudaFuncSetAttribute(up_kernel, cudaFuncAttributeMaxDynamicSharedMemorySize, SMEM_EPI);

    route_kernel<<<1, 256>>>(mapped);

    dim3 g1(MTILES, HID / 64);   // 40 x 48, x=mtile for L2 weight reuse
    up_kernel<<<g1, 256, SMEM_EPI>>>(x, Wg, bg, Wi, bi);

    dim3 g2(MTILES, CDIM / 128); // 40 x 6
    down_kernel<<<g2, 256, SMEM_LOOP>>>(Wo, bo, out);
}